// round 2
// baseline (speedup 1.0000x reference)
#include <cuda_runtime.h>
#include <cuda_bf16.h>

// Scratch accumulators: [G][4] = {count, sum_col11, sum_col24, pad}
#define GMAX 8192
__device__ float g_acc[GMAX * 4];

__global__ void zero_acc_kernel(int n) {
    int i = blockIdx.x * blockDim.x + threadIdx.x;
    if (i < n) g_acc[i] = 0.0f;
}

// Segmented sum over sorted batch ids. One thread per node.
// Warp-level segmented reduction: only run leaders do global atomics.
__global__ void seg_reduce_kernel(const float* __restrict__ nf,
                                  const int* __restrict__ batch,
                                  int N) {
    int i = blockIdx.x * blockDim.x + threadIdx.x;
    int lane = threadIdx.x & 31;

    int g = -1;
    float v0 = 0.0f, v1 = 0.0f, c = 0.0f;
    if (i < N) {
        g = batch[i];
        const float* row = nf + (size_t)i * 128;
        v0 = __ldg(row + 11);   // MODIFIER_COL
        v1 = __ldg(row + 24);   // OWNER_COL
        c  = 1.0f;
    }

    // Lanes with equal g form contiguous runs (batch is sorted).
    unsigned peers  = __match_any_sync(0xffffffffu, g);
    int      leader = __ffs(peers) - 1;
    int      cnt    = __popc(peers);

    // Segmented shfl-down reduce within each contiguous run.
    #pragma unroll
    for (int off = 16; off > 0; off >>= 1) {
        float t0 = __shfl_down_sync(0xffffffffu, v0, off);
        float t1 = __shfl_down_sync(0xffffffffu, v1, off);
        float tc = __shfl_down_sync(0xffffffffu, c,  off);
        if (lane + off < leader + cnt) { v0 += t0; v1 += t1; c += tc; }
    }

    if (lane == leader && g >= 0) {
        atomicAdd(&g_acc[g * 4 + 0], c);
        atomicAdd(&g_acc[g * 4 + 1], v0);
        atomicAdd(&g_acc[g * 4 + 2], v1);
    }
}

// Per-graph tiny MLP: a = 1 - mean; h = relu(a @ W1^T + b1); score = sigmoid(h @ W2^T + b2)
__global__ void mlp_kernel(const float* __restrict__ W1,   // [32, 2]
                           const float* __restrict__ b1,   // [32]
                           const float* __restrict__ W2,   // [1, 32]
                           const float* __restrict__ b2,   // [1]
                           float* __restrict__ out, int G) {
    int g = blockIdx.x * blockDim.x + threadIdx.x;
    if (g >= G) return;

    float c     = g_acc[g * 4 + 0];
    float denom = fmaxf(c, 1.0f);
    float a0 = 1.0f - g_acc[g * 4 + 1] / denom;
    float a1 = 1.0f - g_acc[g * 4 + 2] / denom;

    float acc = __ldg(b2);
    #pragma unroll
    for (int j = 0; j < 32; j++) {
        float h = fmaf(a0, __ldg(W1 + j * 2 + 0),
                  fmaf(a1, __ldg(W1 + j * 2 + 1), __ldg(b1 + j)));
        h = fmaxf(h, 0.0f);
        acc = fmaf(h, __ldg(W2 + j), acc);
    }
    float score = 1.0f / (1.0f + __expf(-acc));
    out[g] = (c > 0.0f) ? score : 0.0f;
}

extern "C" void kernel_launch(void* const* d_in, const int* in_sizes, int n_in,
                              void* d_out, int out_size) {
    // metadata order: node_features, batch, graph_embedding(unused), W1, b1, W2, b2, [num_graphs]
    const float* nf    = (const float*)d_in[0];
    const int*   batch = (const int*)d_in[1];
    const float* W1    = (const float*)d_in[3];
    const float* b1    = (const float*)d_in[4];
    const float* W2    = (const float*)d_in[5];
    const float* b2    = (const float*)d_in[6];
    float*       out   = (float*)d_out;

    int N = in_sizes[1];        // number of nodes (batch length)
    int G = out_size;           // number of graphs
    if (G > GMAX) G = GMAX;

    zero_acc_kernel<<<(G * 4 + 255) / 256, 256>>>(G * 4);
    seg_reduce_kernel<<<(N + 255) / 256, 256>>>(nf, batch, N);
    mlp_kernel<<<(G + 255) / 256, 256>>>(W1, b1, W2, b2, out, G);
}